// round 2
// baseline (speedup 1.0000x reference)
#include <cuda_runtime.h>
#include <cstdint>

// ---------------------------------------------------------------------------
// Problem constants
//   x  : [8, 2048, 512]  fp32
//   Wq/Wk/Wv : [512, 512], bq/bk/bv : [512]
//   out: [8, 2048, 1024] = concat(x, attn_out)
// ---------------------------------------------------------------------------
#define BATCH   8
#define SEQ     2048
#define DMODEL  512
#define ROWS    (BATCH * SEQ)        // 16384
#define SCALE   0.044194173824159216f // 1/sqrt(512)

// Scratch (allocation-free rule: __device__ globals)
__device__ float g_Q[ROWS * DMODEL];
__device__ float g_K[ROWS * DMODEL];
__device__ float g_V[ROWS * DMODEL];

// ---------------------------------------------------------------------------
// Kernel 1: copy x into out[..., 0:512]
// ---------------------------------------------------------------------------
__global__ void __launch_bounds__(256) copy_x_kernel(const float* __restrict__ x,
                                                     float* __restrict__ out) {
    int idx = blockIdx.x * 256 + threadIdx.x;     // float4 index, 2,097,152 total
    int row = idx >> 7;                           // 128 float4 per 512-float row
    int c   = (idx & 127) * 4;
    *(float4*)(out + (size_t)row * 1024 + c) =
        *(const float4*)(x + (size_t)row * 512 + c);
}

// ---------------------------------------------------------------------------
// Kernel 2: QKV projection GEMM.  C[16384,512] = X[16384,512] @ W[512,512] + b
// 128x128 tile, BK=8, 256 threads, 8x8 micro-tile per thread.
// grid = (4, 128, 3); z selects (Wq,bq,g_Q) / (Wk,bk,g_K) / (Wv,bv,g_V)
// ---------------------------------------------------------------------------
__global__ void __launch_bounds__(256) qkv_gemm_kernel(
    const float* __restrict__ X,
    const float* __restrict__ W0, const float* __restrict__ b0,
    const float* __restrict__ W1, const float* __restrict__ b1,
    const float* __restrict__ W2, const float* __restrict__ b2) {

    const float* W; const float* bias; float* C;
    if (blockIdx.z == 0)      { W = W0; bias = b0; C = g_Q; }
    else if (blockIdx.z == 1) { W = W1; bias = b1; C = g_K; }
    else                      { W = W2; bias = b2; C = g_V; }

    __shared__ float As[8][128];   // A tile, transposed: As[k][m]
    __shared__ float Bs[8][128];   // B tile: Bs[k][n]

    const int t  = threadIdx.x;
    const int tx = t & 15;         // N direction (16)
    const int ty = t >> 4;         // M direction (16)
    const int bm = blockIdx.y;     // 128 M-tiles
    const int bn = blockIdx.x;     // 4 N-tiles

    float acc[8][8];
#pragma unroll
    for (int i = 0; i < 8; i++)
#pragma unroll
        for (int j = 0; j < 8; j++) acc[i][j] = 0.f;

    const int arow = t >> 1;            // 0..127
    const int acol = (t & 1) * 4;       // 0 or 4
    const int brow = t >> 5;            // 0..7
    const int bcol = (t & 31) * 4;      // 0..124

    const float* Ag = X + (size_t)(bm * 128 + arow) * 512 + acol;
    const float* Bg = W + (size_t)brow * 512 + bn * 128 + bcol;

    for (int k0 = 0; k0 < 512; k0 += 8) {
        float4 a  = *(const float4*)(Ag + k0);
        float4 bv = *(const float4*)(Bg + (size_t)k0 * 512);
        __syncthreads();                 // previous iter's reads done
        As[acol + 0][arow] = a.x;
        As[acol + 1][arow] = a.y;
        As[acol + 2][arow] = a.z;
        As[acol + 3][arow] = a.w;
        *(float4*)&Bs[brow][bcol] = bv;
        __syncthreads();

#pragma unroll
        for (int kk = 0; kk < 8; kk++) {
            float4 a0 = *(const float4*)&As[kk][ty * 4];
            float4 a1 = *(const float4*)&As[kk][ty * 4 + 64];
            float4 c0 = *(const float4*)&Bs[kk][tx * 4];
            float4 c1 = *(const float4*)&Bs[kk][tx * 4 + 64];
            float av[8] = {a0.x, a0.y, a0.z, a0.w, a1.x, a1.y, a1.z, a1.w};
            float bw[8] = {c0.x, c0.y, c0.z, c0.w, c1.x, c1.y, c1.z, c1.w};
#pragma unroll
            for (int i = 0; i < 8; i++)
#pragma unroll
                for (int j = 0; j < 8; j++) acc[i][j] += av[i] * bw[j];
        }
    }

    // Epilogue: rows ty*4 + {0..3, 64..67}; cols tx*4 + {0..3, 64..67}
    const int col0 = bn * 128 + tx * 4;
    float4 bias0 = *(const float4*)(bias + col0);
    float4 bias1 = *(const float4*)(bias + col0 + 64);
#pragma unroll
    for (int rm = 0; rm < 8; rm++) {
        int row = bm * 128 + ty * 4 + (rm & 3) + ((rm >> 2) * 64);
        float* Crow = C + (size_t)row * 512;
        float4 r0 = make_float4(acc[rm][0] + bias0.x, acc[rm][1] + bias0.y,
                                acc[rm][2] + bias0.z, acc[rm][3] + bias0.w);
        float4 r1 = make_float4(acc[rm][4] + bias1.x, acc[rm][5] + bias1.y,
                                acc[rm][6] + bias1.z, acc[rm][7] + bias1.w);
        *(float4*)(Crow + col0)      = r0;
        *(float4*)(Crow + col0 + 64) = r1;
    }
}

// ---------------------------------------------------------------------------
// Kernel 3: causal flash attention, fp32, writes out[..., 512:1024]
// Block = 32 queries of one batch, 256 threads.
// Thread (i = t/8, g = t%8) owns query row i's d-subset {g*4 + 32k + c}
// (strided float4 chunks -> all-32-bank conflict-free LDS with 4-way broadcast).
// Q and O live entirely in registers (64 regs each). K/V tiles of 16 rows
// share one 32KB smem buffer. Online softmax replicated per row via shfl.
// ---------------------------------------------------------------------------
#define BQ 32
#define BK 16

__global__ void __launch_bounds__(256) attn_kernel(float* __restrict__ out) {
    __shared__ float KVs[BK][DMODEL];   // 32 KB, reused for K then V

    const int t  = threadIdx.x;
    const int g  = t & 7;
    const int i  = t >> 3;                       // query row within tile
    const int b  = blockIdx.y;
    const int qt = (gridDim.x - 1) - blockIdx.x; // heaviest tiles first
    const int q0 = qt * BQ;
    const int qi = q0 + i;

    const float* Kb = g_K + (size_t)b * SEQ * DMODEL;
    const float* Vb = g_V + (size_t)b * SEQ * DMODEL;

    // Q row -> registers (strided subset)
    float4 q[16];
    {
        const float* qrow = g_Q + ((size_t)b * SEQ + qi) * DMODEL + g * 4;
#pragma unroll
        for (int k = 0; k < 16; k++) q[k] = *(const float4*)(qrow + k * 32);
    }

    float4 o[16];
#pragma unroll
    for (int k = 0; k < 16; k++) o[k] = make_float4(0.f, 0.f, 0.f, 0.f);

    float m = -INFINITY;
    float l = 0.f;

    const int ntiles = (q0 + BQ) / BK;   // exact: covers keys 0..q0+31

    for (int kt = 0; kt < ntiles; kt++) {
        const int kbase = kt * BK;

        // --- load K tile ---
        __syncthreads();   // prior PV reads of KVs complete
#pragma unroll
        for (int idx = t; idx < BK * (DMODEL / 4); idx += 256) {
            int row = idx >> 7;
            int c4  = (idx & 127) * 4;
            *(float4*)&KVs[row][c4] =
                *(const float4*)(Kb + (size_t)(kbase + row) * DMODEL + c4);
        }
        __syncthreads();

        // --- scores: partial dot over this thread's d-subset, shfl-reduce ---
        float s[BK];
#pragma unroll
        for (int j = 0; j < BK; j++) {
            float acc = 0.f;
#pragma unroll
            for (int k = 0; k < 16; k++) {
                float4 kv = *(const float4*)&KVs[j][g * 4 + k * 32];
                acc += q[k].x * kv.x + q[k].y * kv.y + q[k].z * kv.z + q[k].w * kv.w;
            }
            acc += __shfl_xor_sync(0xffffffffu, acc, 1);
            acc += __shfl_xor_sync(0xffffffffu, acc, 2);
            acc += __shfl_xor_sync(0xffffffffu, acc, 4);
            s[j] = (kbase + j <= qi) ? acc * SCALE : -INFINITY;
        }

        // --- online softmax (replicated across the 8 g-lanes of a row) ---
        float mt = s[0];
#pragma unroll
        for (int j = 1; j < BK; j++) mt = fmaxf(mt, s[j]);
        float m_new = fmaxf(m, mt);
        float alpha = __expf(m - m_new);    // exp(-inf)=0 on first tile
        float p[BK];
        float psum = 0.f;
#pragma unroll
        for (int j = 0; j < BK; j++) { p[j] = __expf(s[j] - m_new); psum += p[j]; }
        l = l * alpha + psum;
        m = m_new;
#pragma unroll
        for (int k = 0; k < 16; k++) {
            o[k].x *= alpha; o[k].y *= alpha; o[k].z *= alpha; o[k].w *= alpha;
        }

        // --- load V tile (same buffer) ---
        __syncthreads();
#pragma unroll
        for (int idx = t; idx < BK * (DMODEL / 4); idx += 256) {
            int row = idx >> 7;
            int c4  = (idx & 127) * 4;
            *(float4*)&KVs[row][c4] =
                *(const float4*)(Vb + (size_t)(kbase + row) * DMODEL + c4);
        }
        __syncthreads();

        // --- PV accumulate ---
#pragma unroll
        for (int j = 0; j < BK; j++) {
            float pj = p[j];
#pragma unroll
            for (int k = 0; k < 16; k++) {
                float4 vv = *(const float4*)&KVs[j][g * 4 + k * 32];
                o[k].x += pj * vv.x; o[k].y += pj * vv.y;
                o[k].z += pj * vv.z; o[k].w += pj * vv.w;
            }
        }
    }

    // --- normalize + write out[..., 512 + d] ---
    const float inv = 1.f / l;
    float* orow = out + ((size_t)b * SEQ + qi) * 1024 + 512 + g * 4;
#pragma unroll
    for (int k = 0; k < 16; k++) {
        float4 v = make_float4(o[k].x * inv, o[k].y * inv, o[k].z * inv, o[k].w * inv);
        *(float4*)(orow + k * 32) = v;
    }
}

// ---------------------------------------------------------------------------
// Launch (graph-capturable: kernel launches only, default stream => serialized)
// ---------------------------------------------------------------------------
extern "C" void kernel_launch(void* const* d_in, const int* in_sizes, int n_in,
                              void* d_out, int out_size) {
    const float* x  = (const float*)d_in[0];
    const float* Wq = (const float*)d_in[1];
    const float* bq = (const float*)d_in[2];
    const float* Wk = (const float*)d_in[3];
    const float* bk = (const float*)d_in[4];
    const float* Wv = (const float*)d_in[5];
    const float* bv = (const float*)d_in[6];
    float* out = (float*)d_out;

    // out[..., 0:512] = x
    copy_x_kernel<<<ROWS * (DMODEL / 4) / 256, 256>>>(x, out);

    // Q/K/V = x @ W* + b*
    qkv_gemm_kernel<<<dim3(4, 128, 3), 256>>>(x, Wq, bq, Wk, bk, Wv, bv);

    // causal attention -> out[..., 512:1024]
    attn_kernel<<<dim3(SEQ / BQ, BATCH), 256>>>(out);
}

// round 7
// speedup vs baseline: 5.5831x; 5.5831x over previous
#include <cuda_runtime.h>
#include <cstdint>
#include <math.h>

#define BATCH   8
#define SEQ     2048
#define DMODEL  512
#define ROWS    (BATCH * SEQ)
#define SCALE   0.044194173824159216f

__device__ float g_Q[(size_t)ROWS * DMODEL];
__device__ float g_K[(size_t)ROWS * DMODEL];
__device__ float g_V[(size_t)ROWS * DMODEL];
__device__ float g_S[(size_t)BATCH * SEQ * SEQ];

__device__ __forceinline__ float tf32r(float x) {
    uint32_t u;
    asm("cvt.rna.tf32.f32 %0, %1;" : "=r"(u) : "f"(x));
    return __uint_as_float(u);
}
__device__ __forceinline__ void mma8(float c[4], const uint32_t a[4],
                                     uint32_t b0, uint32_t b1) {
    asm volatile(
        "mma.sync.aligned.m16n8k8.row.col.f32.tf32.tf32.f32 "
        "{%0,%1,%2,%3}, {%4,%5,%6,%7}, {%8,%9}, {%0,%1,%2,%3};"
        : "+f"(c[0]), "+f"(c[1]), "+f"(c[2]), "+f"(c[3])
        : "r"(a[0]), "r"(a[1]), "r"(a[2]), "r"(a[3]), "r"(b0), "r"(b1));
}

#define TSTRIDE 36
#define TILE_FLOATS (128 * TSTRIDE)
#define SMEM_BYTES  (4 * TILE_FLOATS * 4)   // 73728 B

// gmem [row][col], col contiguous -> regs (tile rows r0.., k chunk c0..)
__device__ __forceinline__ void ldgTile(const float* G, int ld, int r0, int c0,
                                        float4 r[4]) {
    const int t = threadIdx.x, row = t >> 3, c4 = (t & 7) * 4;
#pragma unroll
    for (int i = 0; i < 4; i++)
        r[i] = *(const float4*)(G + (size_t)(r0 + row + i * 32) * ld + c0 + c4);
}
__device__ __forceinline__ void stsTile(float* S, const float4 r[4]) {
    const int t = threadIdx.x, row = t >> 3, c4 = (t & 7) * 4;
#pragma unroll
    for (int i = 0; i < 4; i++) {
        float4 v = make_float4(tf32r(r[i].x), tf32r(r[i].y),
                               tf32r(r[i].z), tf32r(r[i].w));
        *(float4*)&S[(row + i * 32) * TSTRIDE + c4] = v;
    }
}
// gmem [k][n], n contiguous -> transposed into smem [n][k]
__device__ __forceinline__ void ldgTileT(const float* G, int ld, int k0, int n0,
                                         float r[4][4]) {
    const int t = threadIdx.x, n = t & 127, kb = t >> 7;
#pragma unroll
    for (int it = 0; it < 4; it++) {
        int kr = k0 + (kb + it * 2) * 4;
#pragma unroll
        for (int j = 0; j < 4; j++)
            r[it][j] = G[(size_t)(kr + j) * ld + n0 + n];
    }
}
__device__ __forceinline__ void stsTileT(float* S, const float r[4][4]) {
    const int t = threadIdx.x, n = t & 127, kb = t >> 7;
#pragma unroll
    for (int it = 0; it < 4; it++) {
        float4 v = make_float4(tf32r(r[it][0]), tf32r(r[it][1]),
                               tf32r(r[it][2]), tf32r(r[it][3]));
        *(float4*)&S[n * TSTRIDE + (kb + it * 2) * 4] = v;
    }
}

// C[128,128] = A[128,32*kChunks] * B; 8 warps (4Mx2N), warp tile 32x64.
// Fragments via direct LDS per the PTX mma.m16n8k8.tf32 layout:
//   A: a0=(g,t) a1=(g+8,t) a2=(g,t+4) a3=(g+8,t+4)
//   B: b0=(k=t,n=g) b1=(k=t+4,n=g)          [g=lane>>2, t=lane&3]
// stride 36 (== 4 mod 32): lane L -> bank (L/4)*4+L%4, conflict-free.
template <bool BT>
__device__ __forceinline__ void gemm_core(float* sm,
                                          const float* A, int lda, int m0,
                                          const float* B, int ldb, int n0,
                                          int kChunks, float acc[2][8][4]) {
    float* As = sm;
    float* Bs = sm + 2 * TILE_FLOATS;
    const int lane = threadIdx.x & 31, wid = threadIdx.x >> 5;
    const int wm = wid >> 1, wn = wid & 1;
    const int g = lane >> 2, tt = lane & 3;

#pragma unroll
    for (int i = 0; i < 2; i++)
#pragma unroll
        for (int j = 0; j < 8; j++)
#pragma unroll
            for (int k = 0; k < 4; k++) acc[i][j][k] = 0.f;

    float4 ra[4]; float rbt[4][4]; float4 rbs[4];
    ldgTile(A, lda, m0, 0, ra);
    if (BT) ldgTileT(B, ldb, 0, n0, rbt); else ldgTile(B, ldb, n0, 0, rbs);
    stsTile(As, ra);
    if (BT) stsTileT(Bs, rbt); else stsTile(Bs, rbs);
    __syncthreads();

    for (int c = 0; c < kChunks; c++) {
        if (c + 1 < kChunks) {
            ldgTile(A, lda, m0, (c + 1) * 32, ra);
            if (BT) ldgTileT(B, ldb, (c + 1) * 32, n0, rbt);
            else    ldgTile(B, ldb, n0, (c + 1) * 32, rbs);
        }
        const float* Ab = As + (c & 1) * TILE_FLOATS + (wm * 32 + g) * TSTRIDE + tt;
        const float* Bb = Bs + (c & 1) * TILE_FLOATS + (wn * 64 + g) * TSTRIDE + tt;
#pragma unroll
        for (int ks = 0; ks < 4; ks++) {
            uint32_t a[2][4];
#pragma unroll
            for (int mi = 0; mi < 2; mi++) {
                const float* p = Ab + mi * (16 * TSTRIDE) + ks * 8;
                a[mi][0] = __float_as_uint(p[0]);
                a[mi][1] = __float_as_uint(p[8 * TSTRIDE]);
                a[mi][2] = __float_as_uint(p[4]);
                a[mi][3] = __float_as_uint(p[8 * TSTRIDE + 4]);
            }
#pragma unroll
            for (int nj = 0; nj < 8; nj++) {
                const float* p = Bb + nj * (8 * TSTRIDE) + ks * 8;
                uint32_t b0 = __float_as_uint(p[0]);
                uint32_t b1 = __float_as_uint(p[4]);
#pragma unroll
                for (int mi = 0; mi < 2; mi++)
                    mma8(acc[mi][nj], a[mi], b0, b1);
            }
        }
        if (c + 1 < kChunks) {
            __syncthreads();
            stsTile(As + ((c + 1) & 1) * TILE_FLOATS, ra);
            if (BT) stsTileT(Bs + ((c + 1) & 1) * TILE_FLOATS, rbt);
            else    stsTile (Bs + ((c + 1) & 1) * TILE_FLOATS, rbs);
            __syncthreads();
        }
    }
}
// acc coords: row = m0+wm*32+mi*16+(lane>>2) [+8 for c2/c3],
//             col = n0+wn*64+ni*8+(lane&3)*2, (c0,c1) adjacent cols.

__global__ void __launch_bounds__(256) qkv_gemm_tc(
    const float* __restrict__ x,
    const float* __restrict__ W0, const float* __restrict__ b0,
    const float* __restrict__ W1, const float* __restrict__ b1,
    const float* __restrict__ W2, const float* __restrict__ b2) {
    extern __shared__ float sm[];
    const float* W; const float* bias; float* C;
    if (blockIdx.z == 0)      { W = W0; bias = b0; C = g_Q; }
    else if (blockIdx.z == 1) { W = W1; bias = b1; C = g_K; }
    else                      { W = W2; bias = b2; C = g_V; }
    const int m0 = blockIdx.y * 128, n0 = blockIdx.x * 128;
    float acc[2][8][4];
    gemm_core<true>(sm, x, DMODEL, m0, W, DMODEL, n0, DMODEL / 32, acc);

    const int lane = threadIdx.x & 31, wid = threadIdx.x >> 5;
    const int wm = wid >> 1, wn = wid & 1;
    const int r = lane >> 2, cb = (lane & 3) * 2;
#pragma unroll
    for (int mi = 0; mi < 2; mi++)
#pragma unroll
        for (int ni = 0; ni < 8; ni++) {
            int row = m0 + wm * 32 + mi * 16 + r;
            int col = n0 + wn * 64 + ni * 8 + cb;
            float2 bb = *(const float2*)&bias[col];
            *(float2*)(C + (size_t)row * DMODEL + col) =
                make_float2(acc[mi][ni][0] + bb.x, acc[mi][ni][1] + bb.y);
            *(float2*)(C + (size_t)(row + 8) * DMODEL + col) =
                make_float2(acc[mi][ni][2] + bb.x, acc[mi][ni][3] + bb.y);
        }
}

__global__ void __launch_bounds__(256) s_gemm_tc() {
    if (blockIdx.x > blockIdx.y) return;   // strictly-future tile: skip
    extern __shared__ float sm[];
    const int z = blockIdx.z;
    const int m0 = blockIdx.y * 128, n0 = blockIdx.x * 128;
    const float* Q = g_Q + (size_t)z * SEQ * DMODEL;
    const float* K = g_K + (size_t)z * SEQ * DMODEL;
    float* S = g_S + (size_t)z * SEQ * SEQ;
    float acc[2][8][4];
    gemm_core<false>(sm, Q, DMODEL, m0, K, DMODEL, n0, DMODEL / 32, acc);

    const int lane = threadIdx.x & 31, wid = threadIdx.x >> 5;
    const int wm = wid >> 1, wn = wid & 1;
    const int r = lane >> 2, cb = (lane & 3) * 2;
#pragma unroll
    for (int mi = 0; mi < 2; mi++)
#pragma unroll
        for (int ni = 0; ni < 8; ni++) {
            int row = m0 + wm * 32 + mi * 16 + r;
            int col = n0 + wn * 64 + ni * 8 + cb;
            *(float2*)(S + (size_t)row * SEQ + col) =
                make_float2(acc[mi][ni][0] * SCALE, acc[mi][ni][1] * SCALE);
            *(float2*)(S + (size_t)(row + 8) * SEQ + col) =
                make_float2(acc[mi][ni][2] * SCALE, acc[mi][ni][3] * SCALE);
        }
}

// row softmax in place; zero-fills (q, wlen) so PV reads whole 128-tiles.
__global__ void __launch_bounds__(256) softmax_kernel() {
    __shared__ float sh[8];
    __shared__ float bcast;
    const int q = blockIdx.x, z = blockIdx.y, t = threadIdx.x;
    float* Srow = g_S + ((size_t)z * SEQ + q) * SEQ;
    const int len  = q + 1;
    const int wlen = ((q >> 7) + 1) << 7;
    const int n    = (wlen + 255) >> 8;   // FIX: ceil — was floor, dropped last
                                          // 128 cols for wlen == 128 (mod 256)

    float v[8];
    float m = -INFINITY;
#pragma unroll 8
    for (int j = 0; j < n; j++) {
        int i = t + j * 256;
        float x = (i < len) ? Srow[i] : -INFINITY;
        v[j] = x; m = fmaxf(m, x);
    }
#pragma unroll
    for (int o = 16; o; o >>= 1) m = fmaxf(m, __shfl_xor_sync(~0u, m, o));
    if ((t & 31) == 0) sh[t >> 5] = m;
    __syncthreads();
    if (t == 0) {
        float mm = sh[0];
        for (int w = 1; w < 8; w++) mm = fmaxf(mm, sh[w]);
        bcast = mm;
    }
    __syncthreads();
    m = bcast;

    float s = 0.f;
#pragma unroll 8
    for (int j = 0; j < n; j++) { v[j] = __expf(v[j] - m); s += v[j]; }
#pragma unroll
    for (int o = 16; o; o >>= 1) s += __shfl_xor_sync(~0u, s, o);
    __syncthreads();
    if ((t & 31) == 0) sh[t >> 5] = s;
    __syncthreads();
    if (t == 0) {
        float ss = 0.f;
        for (int w = 0; w < 8; w++) ss += sh[w];
        bcast = 1.f / ss;
    }
    __syncthreads();
    const float inv = bcast;
#pragma unroll 8
    for (int j = 0; j < n; j++) {
        int i = t + j * 256;
        if (i < wlen) Srow[i] = v[j] * inv;   // exp(-inf)*inv = 0 pads tail
    }
}

__global__ void __launch_bounds__(256) pv_gemm_tc(float* __restrict__ out) {
    extern __shared__ float sm[];
    const int z = blockIdx.z, qt = blockIdx.y;
    const int m0 = qt * 128, n0 = blockIdx.x * 128;
    const float* P = g_S + (size_t)z * SEQ * SEQ;
    const float* V = g_V + (size_t)z * SEQ * DMODEL;
    float acc[2][8][4];
    gemm_core<true>(sm, P, SEQ, m0, V, DMODEL, n0, (qt + 1) * 4, acc);

    const int lane = threadIdx.x & 31, wid = threadIdx.x >> 5;
    const int wm = wid >> 1, wn = wid & 1;
    const int r = lane >> 2, cb = (lane & 3) * 2;
#pragma unroll
    for (int mi = 0; mi < 2; mi++)
#pragma unroll
        for (int ni = 0; ni < 8; ni++) {
            int row = m0 + wm * 32 + mi * 16 + r;
            int col = n0 + wn * 64 + ni * 8 + cb;
            *(float2*)(out + ((size_t)z * SEQ + row) * 1024 + 512 + col) =
                make_float2(acc[mi][ni][0], acc[mi][ni][1]);
            *(float2*)(out + ((size_t)z * SEQ + row + 8) * 1024 + 512 + col) =
                make_float2(acc[mi][ni][2], acc[mi][ni][3]);
        }
}

__global__ void __launch_bounds__(256) copy_x_kernel(const float* __restrict__ x,
                                                     float* __restrict__ out) {
    int idx = blockIdx.x * 256 + threadIdx.x;
    int row = idx >> 7, c = (idx & 127) * 4;
    *(float4*)(out + (size_t)row * 1024 + c) =
        *(const float4*)(x + (size_t)row * 512 + c);
}

extern "C" void kernel_launch(void* const* d_in, const int* in_sizes, int n_in,
                              void* d_out, int out_size) {
    const float* x  = (const float*)d_in[0];
    const float* Wq = (const float*)d_in[1];
    const float* bq = (const float*)d_in[2];
    const float* Wk = (const float*)d_in[3];
    const float* bk = (const float*)d_in[4];
    const float* Wv = (const float*)d_in[5];
    const float* bv = (const float*)d_in[6];
    float* out = (float*)d_out;

    cudaFuncSetAttribute(qkv_gemm_tc, cudaFuncAttributeMaxDynamicSharedMemorySize, SMEM_BYTES);
    cudaFuncSetAttribute(s_gemm_tc,   cudaFuncAttributeMaxDynamicSharedMemorySize, SMEM_BYTES);
    cudaFuncSetAttribute(pv_gemm_tc,  cudaFuncAttributeMaxDynamicSharedMemorySize, SMEM_BYTES);

    copy_x_kernel<<<ROWS * (DMODEL / 4) / 256, 256>>>(x, out);
    qkv_gemm_tc<<<dim3(4, 128, 3), 256, SMEM_BYTES>>>(x, Wq, bq, Wk, bk, Wv, bv);
    s_gemm_tc<<<dim3(16, 16, 8), 256, SMEM_BYTES>>>();
    softmax_kernel<<<dim3(SEQ, BATCH), 256>>>();
    pv_gemm_tc<<<dim3(4, 16, 8), 256, SMEM_BYTES>>>(out);
}